// round 3
// baseline (speedup 1.0000x reference)
#include <cuda_runtime.h>
#include <cuda_bf16.h>
#include <cstdint>

#define HH 1024
#define BB 64
#define LLEN 1024
#define VV 50257
#define NLAY 2

// ---------------- split-bf16 helpers ----------------
__device__ __forceinline__ uint32_t pack_bf16x2(float lo, float hi) {
    uint32_t r;
    asm("cvt.rn.satfinite.bf16x2.f32 %0, %1, %2;" : "=r"(r) : "f"(hi), "f"(lo));
    return r;
}

// float2 -> hi bf16x2 + residual lo bf16x2
__device__ __forceinline__ void split2(float2 v, uint32_t& hi, uint32_t& lo) {
    hi = pack_bf16x2(v.x, v.y);
    float lx = v.x - __uint_as_float(hi << 16);
    float ly = v.y - __uint_as_float(hi & 0xFFFF0000u);
    lo = pack_bf16x2(lx, ly);
}

__device__ __forceinline__ void mma16816(float* c,
                                         uint32_t a0, uint32_t a1, uint32_t a2, uint32_t a3,
                                         uint32_t b0, uint32_t b1) {
    asm volatile(
        "mma.sync.aligned.m16n8k16.row.col.f32.bf16.bf16.f32 "
        "{%0,%1,%2,%3}, {%4,%5,%6,%7}, {%8,%9}, {%0,%1,%2,%3};"
        : "+f"(c[0]), "+f"(c[1]), "+f"(c[2]), "+f"(c[3])
        : "r"(a0), "r"(a1), "r"(a2), "r"(a3), "r"(b0), "r"(b1));
}

// ---------------- scratch ----------------
// X 65536 | GX 196608 | GH 196608 | E 65536 | CIN 131072 | COUT 65536
__device__ float g_scratch[720896];

// ================= split-bf16 HMMA GEMM =================
// out[n][m] = act( sum_k W[m,k]*X[n,k] + bias[m] ),  n = 0..63 (batch).
// 256 threads = 8 warps; warp w owns rows [blk*128 + w*16, +16).
// blockIdx.y == 1 selects the second parameter set (GRU ih/hh pairing).
__global__ void __launch_bounds__(256) k_gemm(
    const float* __restrict__ W, const float* __restrict__ X,
    const float* __restrict__ bias, float* __restrict__ out,
    int Nout, int K, int act,
    const float* W2, const float* X2, const float* bias2, float* out2)
{
    if (blockIdx.y == 1) { W = W2; X = X2; bias = bias2; out = out2; }

    const int tid  = threadIdx.x;
    const int wid  = tid >> 5;
    const int lane = tid & 31;
    const int g    = lane >> 2;     // group id 0..7
    const int tig  = lane & 3;      // thread-in-group 0..3

    const int m_g  = blockIdx.x * 128 + wid * 16 + g;  // rows for a0/a2, c0/c1
    const int m_g8 = m_g + 8;                          // rows for a1/a3, c2/c3
    const bool v0 = (m_g  < Nout);
    const bool v1 = (m_g8 < Nout);

    const float* Wr0 = W + (size_t)(v0 ? m_g  : 0) * K;
    const float* Wr1 = W + (size_t)(v1 ? m_g8 : 0) * K;

    float acc[8][4];
#pragma unroll
    for (int nf = 0; nf < 8; ++nf)
#pragma unroll
        for (int j = 0; j < 4; ++j) acc[nf][j] = 0.f;

    const float2 z2 = make_float2(0.f, 0.f);

    for (int k0 = 0; k0 < K; k0 += 16) {
        // ---- A fragment: W rows, split to hi/lo ----
        float2 a00 = v0 ? __ldg((const float2*)(Wr0 + k0 + tig * 2))     : z2;
        float2 a01 = v0 ? __ldg((const float2*)(Wr0 + k0 + tig * 2 + 8)) : z2;
        float2 a10 = v1 ? __ldg((const float2*)(Wr1 + k0 + tig * 2))     : z2;
        float2 a11 = v1 ? __ldg((const float2*)(Wr1 + k0 + tig * 2 + 8)) : z2;

        uint32_t ah0, al0, ah1, al1, ah2, al2, ah3, al3;
        split2(a00, ah0, al0);   // a0: (g,   k0+tig*2..+1)
        split2(a10, ah1, al1);   // a1: (g+8, k0+tig*2..+1)
        split2(a01, ah2, al2);   // a2: (g,   k0+tig*2+8..+9)
        split2(a11, ah3, al3);   // a3: (g+8, k0+tig*2+8..+9)

        // ---- B fragments: X rows (batch), 8 n-fragments ----
#pragma unroll
        for (int nf = 0; nf < 8; ++nf) {
            const float* Xr = X + (size_t)(nf * 8 + g) * K + k0 + tig * 2;
            float2 b0f = __ldg((const float2*)Xr);
            float2 b1f = __ldg((const float2*)(Xr + 8));
            uint32_t bh0, bl0, bh1, bl1;
            split2(b0f, bh0, bl0);
            split2(b1f, bh1, bl1);
            mma16816(acc[nf], ah0, ah1, ah2, ah3, bh0, bh1);  // Ahi * Bhi
            mma16816(acc[nf], ah0, ah1, ah2, ah3, bl0, bl1);  // Ahi * Blo
            mma16816(acc[nf], al0, al1, al2, al3, bh0, bh1);  // Alo * Bhi
        }
    }

    // ---- epilogue ----
    const float b0v = v0 ? bias[m_g]  : 0.f;
    const float b1v = v1 ? bias[m_g8] : 0.f;
#pragma unroll
    for (int nf = 0; nf < 8; ++nf) {
        int n0 = nf * 8 + tig * 2;
        float c0 = acc[nf][0] + b0v;
        float c1 = acc[nf][1] + b0v;
        float c2 = acc[nf][2] + b1v;
        float c3 = acc[nf][3] + b1v;
        if (act) { c0 = tanhf(c0); c1 = tanhf(c1); c2 = tanhf(c2); c3 = tanhf(c3); }
        if (v0) {
            out[(size_t)n0 * Nout + m_g]       = c0;
            out[(size_t)(n0 + 1) * Nout + m_g] = c1;
        }
        if (v1) {
            out[(size_t)n0 * Nout + m_g8]       = c2;
            out[(size_t)(n0 + 1) * Nout + m_g8] = c3;
        }
    }
}

// ================= small kernels =================
__global__ void k_embed(const int* __restrict__ idx, const float* __restrict__ emb,
                        float* __restrict__ x) {
    int b = blockIdx.x;
    const float4* src = (const float4*)(emb + (size_t)idx[b] * HH);
    float4* dst = (float4*)(x + (size_t)b * HH);
    for (int i = threadIdx.x; i < HH / 4; i += blockDim.x) dst[i] = src[i];
}

__global__ void k_gates(const float* __restrict__ gx, const float* __restrict__ gh,
                        const float* __restrict__ hprev,
                        float* __restrict__ out_hid, float* __restrict__ out_next,
                        int next_stride) {
    int i = blockIdx.x * blockDim.x + threadIdx.x;   // 65536 total
    int b = i >> 10, j = i & 1023;
    const float* gxb = gx + (size_t)b * 3072;
    const float* ghb = gh + (size_t)b * 3072;
    float r = 1.f / (1.f + __expf(-(gxb[j] + ghb[j])));
    float z = 1.f / (1.f + __expf(-(gxb[j + 1024] + ghb[j + 1024])));
    float n = tanhf(gxb[j + 2048] + r * ghb[j + 2048]);
    float h = (1.f - z) * n + z * hprev[(size_t)b * 1024 + j];
    out_hid[(size_t)b * 1024 + j] = h;
    out_next[(size_t)b * next_stride + j] = h;
}

__global__ void k_energy(const float* __restrict__ rnn, int rnn_stride,
                         const float* __restrict__ enc, float* __restrict__ E) {
    __shared__ float sx[HH];
    int b = blockIdx.y;
    const float4* src = (const float4*)(rnn + (size_t)b * rnn_stride);
    for (int i = threadIdx.x; i < HH / 4; i += blockDim.x)
        ((float4*)sx)[i] = src[i];
    __syncthreads();
    int wid = threadIdx.x >> 5, lid = threadIdx.x & 31;
    int l = blockIdx.x * 8 + wid;
    const float4* e4 = (const float4*)(enc + ((size_t)l * BB + b) * HH);
    float acc = 0.f;
#pragma unroll
    for (int j = 0; j < 8; ++j) {
        float4 v = __ldg(e4 + lid + j * 32);
        float4 xw = ((const float4*)sx)[lid + j * 32];
        acc += v.x * xw.x + v.y * xw.y + v.z * xw.z + v.w * xw.w;
    }
#pragma unroll
    for (int o = 16; o; o >>= 1) acc += __shfl_xor_sync(0xffffffffu, acc, o);
    if (lid == 0) E[(size_t)b * LLEN + l] = acc;
}

__global__ void k_softmax(float* __restrict__ E, float* __restrict__ attn_out) {
    __shared__ float red[8];
    int b = blockIdx.x;
    float* e = E + (size_t)b * LLEN;
    int tid = threadIdx.x;
    float v[4];
    float m = -1e30f;
#pragma unroll
    for (int j = 0; j < 4; ++j) { v[j] = e[tid + j * 256]; m = fmaxf(m, v[j]); }
#pragma unroll
    for (int o = 16; o; o >>= 1) m = fmaxf(m, __shfl_xor_sync(0xffffffffu, m, o));
    if ((tid & 31) == 0) red[tid >> 5] = m;
    __syncthreads();
    float bm = red[0];
#pragma unroll
    for (int w = 1; w < 8; ++w) bm = fmaxf(bm, red[w]);
    float s = 0.f;
#pragma unroll
    for (int j = 0; j < 4; ++j) { v[j] = __expf(v[j] - bm); s += v[j]; }
#pragma unroll
    for (int o = 16; o; o >>= 1) s += __shfl_xor_sync(0xffffffffu, s, o);
    __syncthreads();
    if ((tid & 31) == 0) red[tid >> 5] = s;
    __syncthreads();
    float bs = 0.f;
#pragma unroll
    for (int w = 0; w < 8; ++w) bs += red[w];
    float inv = 1.f / bs;
#pragma unroll
    for (int j = 0; j < 4; ++j) {
        float a = v[j] * inv;
        e[tid + j * 256] = a;
        attn_out[(size_t)b * LLEN + tid + j * 256] = a;
    }
}

__global__ void k_context(const float* __restrict__ attn, const float* __restrict__ enc,
                          float* __restrict__ ctx, int ctx_stride) {
    __shared__ float sa[LLEN];
    int b = blockIdx.x;
    int h = blockIdx.y * 128 + threadIdx.x;
    for (int i = threadIdx.x; i < LLEN; i += 128)
        sa[i] = attn[(size_t)b * LLEN + i];
    __syncthreads();
    const float* ep = enc + (size_t)b * HH + h;
    float a0 = 0.f, a1 = 0.f, a2 = 0.f, a3 = 0.f;
#pragma unroll 4
    for (int l = 0; l < LLEN; l += 4) {
        a0 += sa[l]     * __ldg(ep + (size_t)(l)     * (BB * HH));
        a1 += sa[l + 1] * __ldg(ep + (size_t)(l + 1) * (BB * HH));
        a2 += sa[l + 2] * __ldg(ep + (size_t)(l + 2) * (BB * HH));
        a3 += sa[l + 3] * __ldg(ep + (size_t)(l + 3) * (BB * HH));
    }
    ctx[(size_t)b * ctx_stride + h] = (a0 + a1) + (a2 + a3);
}

// ================= launcher =================
extern "C" void kernel_launch(void* const* d_in, const int* in_sizes, int n_in,
                              void* d_out, int out_size) {
    const int*   input_seq = (const int*)  d_in[0];
    const float* last_h    = (const float*)d_in[1];
    const float* enc       = (const float*)d_in[2];
    const float* emb       = (const float*)d_in[3];
    const float* W_ih      = (const float*)d_in[4];
    const float* W_hh      = (const float*)d_in[5];
    const float* b_ih      = (const float*)d_in[6];
    const float* b_hh      = (const float*)d_in[7];
    const float* W_concat  = (const float*)d_in[8];
    const float* b_concat  = (const float*)d_in[9];
    const float* W_out     = (const float*)d_in[10];
    const float* b_out     = (const float*)d_in[11];
    float* out = (float*)d_out;

    float* scratch = nullptr;
    cudaGetSymbolAddress((void**)&scratch, g_scratch);
    float* X    = scratch;
    float* GX   = scratch + 65536;
    float* GH   = scratch + 262144;
    float* E    = scratch + 458752;
    float* CIN  = scratch + 524288;   // [rnn_out | ctx], row stride 2048
    float* COUT = scratch + 655360;

    float* out_logits = out;                                    // (B, V)
    float* out_hidden = out + (size_t)BB * VV;                  // (NL, B, H)
    float* out_attn   = out_hidden + (size_t)NLAY * BB * HH;    // (B, 1, L)

    k_embed<<<BB, 256>>>(input_seq, emb, X);

    // GRU layer 0
    k_gemm<<<dim3(24, 2), 256>>>(
        W_ih, X, b_ih, GX, 3072, 1024, 0,
        W_hh, last_h, b_hh, GH);
    k_gates<<<256, 256>>>(GX, GH, last_h, out_hidden, X, 1024);

    // GRU layer 1
    k_gemm<<<dim3(24, 2), 256>>>(
        W_ih + (size_t)3072 * 1024, X, b_ih + 3072, GX, 3072, 1024, 0,
        W_hh + (size_t)3072 * 1024, last_h + (size_t)BB * HH, b_hh + 3072, GH);
    k_gates<<<256, 256>>>(GX, GH, last_h + (size_t)BB * HH,
                          out_hidden + (size_t)BB * HH, CIN, 2048);

    // attention
    k_energy<<<dim3(128, 64), 256>>>(CIN, 2048, enc, E);
    k_softmax<<<64, 256>>>(E, out_attn);
    k_context<<<dim3(64, 8), 128>>>(E, enc, CIN + 1024, 2048);

    // concat_output = tanh(CIN @ W_concat^T + b_concat)
    k_gemm<<<dim3(8, 1), 256>>>(
        W_concat, CIN, b_concat, COUT, 1024, 2048, 1,
        nullptr, nullptr, nullptr, nullptr);

    // logits = COUT @ W_out^T + b_out
    k_gemm<<<dim3(393, 1), 256>>>(
        W_out, COUT, b_out, out_logits, VV, 1024, 0,
        nullptr, nullptr, nullptr, nullptr);

    (void)in_sizes; (void)n_in; (void)out_size;
}

// round 4
// speedup vs baseline: 2.5789x; 2.5789x over previous
#include <cuda_runtime.h>
#include <cuda_bf16.h>
#include <cstdint>

#define HH 1024
#define BB 64
#define LLEN 1024
#define VV 50257

// ---------------- split-bf16 helpers ----------------
__device__ __forceinline__ uint32_t pack_bf16x2(float lo, float hi) {
    uint32_t r;
    asm("cvt.rn.satfinite.bf16x2.f32 %0, %1, %2;" : "=r"(r) : "f"(hi), "f"(lo));
    return r;
}

// float2 -> hi bf16x2 + residual lo bf16x2
__device__ __forceinline__ void split2(float2 v, uint32_t& hi, uint32_t& lo) {
    hi = pack_bf16x2(v.x, v.y);
    float lx = v.x - __uint_as_float(hi << 16);
    float ly = v.y - __uint_as_float(hi & 0xFFFF0000u);
    lo = pack_bf16x2(lx, ly);
}

__device__ __forceinline__ void mma16816(float* c,
                                         uint32_t a0, uint32_t a1, uint32_t a2, uint32_t a3,
                                         uint32_t b0, uint32_t b1) {
    asm volatile(
        "mma.sync.aligned.m16n8k16.row.col.f32.bf16.bf16.f32 "
        "{%0,%1,%2,%3}, {%4,%5,%6,%7}, {%8,%9}, {%0,%1,%2,%3};"
        : "+f"(c[0]), "+f"(c[1]), "+f"(c[2]), "+f"(c[3])
        : "r"(a0), "r"(a1), "r"(a2), "r"(a3), "r"(b0), "r"(b1));
}

// ---------------- scratch layout (floats) ----------------
// X 0 (65536) | XP 65536 (65536) | HP 131072 (65536)
// GX 196608 (4x196608) | GH 983040 (4x196608)
// E 1769472 (65536) | CIN 1835008 (131072) | CINP 1966080 (131072)
// CC 2097152 (4x65536) | COUTP 2359296 (65536)   total 2424832
__device__ float g_scratch[2424832];

// ================= B-operand pack: fp32 -> MMA-ready bf16 hi/lo =================
// One thread produces one uint4 {bh0, bh1, bl0, bl1} for (kstep t, nf, lane).
// Consumer reads P[(t*8 + nf)*32 + lane].
__global__ void __launch_bounds__(256) k_pack(
    const float* __restrict__ s1, float* __restrict__ d1,
    const float* __restrict__ s2, float* __restrict__ d2, int K)
{
    const float* src = blockIdx.y ? s2 : s1;
    float* dst = blockIdx.y ? d2 : d1;
    int i = blockIdx.x * 256 + threadIdx.x;
    int lane = i & 31, nf = (i >> 5) & 7, t = i >> 8;
    int g = lane >> 2, tig = lane & 3;
    int n = nf * 8 + g;
    int k0 = t * 16 + tig * 2;
    float2 v0 = *(const float2*)(src + (size_t)n * K + k0);
    float2 v1 = *(const float2*)(src + (size_t)n * K + k0 + 8);
    uint32_t h0, l0, h1, l1;
    split2(v0, h0, l0);
    split2(v1, h1, l1);
    ((uint4*)dst)[i] = make_uint4(h0, h1, l0, l1);
}

// pack COUT for the W_out GEMM: sum 4 concat K-slices + bias + tanh, then split.
__global__ void __launch_bounds__(256) k_pack_cout(
    const float* __restrict__ cc, const float* __restrict__ bias,
    float* __restrict__ dst)
{
    int i = blockIdx.x * 256 + threadIdx.x;
    int lane = i & 31, nf = (i >> 5) & 7, t = i >> 8;
    int g = lane >> 2, tig = lane & 3;
    int n = nf * 8 + g;
    int k0 = t * 16 + tig * 2;
    size_t base = (size_t)n * HH;
    float e0 = bias[k0], e1 = bias[k0 + 1], e2 = bias[k0 + 8], e3 = bias[k0 + 9];
#pragma unroll
    for (int z = 0; z < 4; ++z) {
        const float* p = cc + (size_t)z * 65536 + base;
        e0 += p[k0]; e1 += p[k0 + 1]; e2 += p[k0 + 8]; e3 += p[k0 + 9];
    }
    e0 = tanhf(e0); e1 = tanhf(e1); e2 = tanhf(e2); e3 = tanhf(e3);
    uint32_t h0, l0, h1, l1;
    split2(make_float2(e0, e1), h0, l0);
    split2(make_float2(e2, e3), h1, l1);
    ((uint4*)dst)[i] = make_uint4(h0, h1, l0, l1);
}

// ================= split-bf16 HMMA GEMM =================
// out[n][m] = sum_k W[m,k]*X[n,k] (+bias[m] if bias), n = 0..63 batch.
// 128 threads = 4 warps; warp owns 32 rows (two 16-row m-tiles).
// blockIdx.y==1 -> second param set; blockIdx.z -> K slice (tps ksteps),
// each slice writes its own 64*Nout output buffer.
__global__ void __launch_bounds__(128) k_gemm(
    const float* __restrict__ W, const uint4* __restrict__ P,
    float* __restrict__ out, int Nout, int K, int tps,
    const float* __restrict__ bias,
    const float* W2, const uint4* P2, float* out2)
{
    if (blockIdx.y == 1) { W = W2; P = P2; out = out2; }

    const int tid = threadIdx.x;
    const int wid = tid >> 5;
    const int lane = tid & 31;
    const int g = lane >> 2;
    const int tig = lane & 3;

    const int mb = blockIdx.x * 128 + wid * 32;
    const int mA0 = mb + g,      mA1 = mb + 8 + g;      // tile 0
    const int mC0 = mb + 16 + g, mC1 = mb + 24 + g;     // tile 1
    const bool vA0 = mA0 < Nout, vA1 = mA1 < Nout;
    const bool vC0 = mC0 < Nout, vC1 = mC1 < Nout;

    const float* WA0 = W + (size_t)(vA0 ? mA0 : 0) * K;
    const float* WA1 = W + (size_t)(vA1 ? mA1 : 0) * K;
    const float* WC0 = W + (size_t)(vC0 ? mC0 : 0) * K;
    const float* WC1 = W + (size_t)(vC1 ? mC1 : 0) * K;

    float acc0[8][4], acc1[8][4];
#pragma unroll
    for (int nf = 0; nf < 8; ++nf)
#pragma unroll
        for (int j = 0; j < 4; ++j) { acc0[nf][j] = 0.f; acc1[nf][j] = 0.f; }

    const int t0 = blockIdx.z * tps;
    const uint4* Pl = P + (size_t)t0 * 256 + lane;
    const float2 z2 = make_float2(0.f, 0.f);

    for (int t = 0; t < tps; ++t) {
        // hoisted B loads (L2-hot, 8 independent LDG.128)
        uint4 b[8];
#pragma unroll
        for (int nf = 0; nf < 8; ++nf)
            b[nf] = __ldg(Pl + (size_t)t * 256 + nf * 32);

        const int k0 = (t0 + t) * 16 + tig * 2;
        float2 fa0 = vA0 ? __ldg((const float2*)(WA0 + k0))     : z2;
        float2 fa2 = vA0 ? __ldg((const float2*)(WA0 + k0 + 8)) : z2;
        float2 fa1 = vA1 ? __ldg((const float2*)(WA1 + k0))     : z2;
        float2 fa3 = vA1 ? __ldg((const float2*)(WA1 + k0 + 8)) : z2;
        float2 fc0 = vC0 ? __ldg((const float2*)(WC0 + k0))     : z2;
        float2 fc2 = vC0 ? __ldg((const float2*)(WC0 + k0 + 8)) : z2;
        float2 fc1 = vC1 ? __ldg((const float2*)(WC1 + k0))     : z2;
        float2 fc3 = vC1 ? __ldg((const float2*)(WC1 + k0 + 8)) : z2;

        uint32_t ah0, al0, ah1, al1, ah2, al2, ah3, al3;
        uint32_t ch0, cl0, ch1, cl1, ch2, cl2, ch3, cl3;
        split2(fa0, ah0, al0); split2(fa1, ah1, al1);
        split2(fa2, ah2, al2); split2(fa3, ah3, al3);
        split2(fc0, ch0, cl0); split2(fc1, ch1, cl1);
        split2(fc2, ch2, cl2); split2(fc3, ch3, cl3);

#pragma unroll
        for (int nf = 0; nf < 8; ++nf) {
            mma16816(acc0[nf], ah0, ah1, ah2, ah3, b[nf].x, b[nf].y);  // Ahi*Bhi
            mma16816(acc1[nf], ch0, ch1, ch2, ch3, b[nf].x, b[nf].y);
            mma16816(acc0[nf], ah0, ah1, ah2, ah3, b[nf].z, b[nf].w);  // Ahi*Blo
            mma16816(acc1[nf], ch0, ch1, ch2, ch3, b[nf].z, b[nf].w);
            mma16816(acc0[nf], al0, al1, al2, al3, b[nf].x, b[nf].y);  // Alo*Bhi
            mma16816(acc1[nf], cl0, cl1, cl2, cl3, b[nf].x, b[nf].y);
        }
    }

    float* os = out + (size_t)blockIdx.z * 64 * Nout;
    const float bA0 = (bias && vA0) ? bias[mA0] : 0.f;
    const float bA1 = (bias && vA1) ? bias[mA1] : 0.f;
    const float bC0 = (bias && vC0) ? bias[mC0] : 0.f;
    const float bC1 = (bias && vC1) ? bias[mC1] : 0.f;
#pragma unroll
    for (int nf = 0; nf < 8; ++nf) {
        const int n0 = nf * 8 + tig * 2;
        if (vA0) {
            os[(size_t)n0 * Nout + mA0]       = acc0[nf][0] + bA0;
            os[(size_t)(n0 + 1) * Nout + mA0] = acc0[nf][1] + bA0;
        }
        if (vA1) {
            os[(size_t)n0 * Nout + mA1]       = acc0[nf][2] + bA1;
            os[(size_t)(n0 + 1) * Nout + mA1] = acc0[nf][3] + bA1;
        }
        if (vC0) {
            os[(size_t)n0 * Nout + mC0]       = acc1[nf][0] + bC0;
            os[(size_t)(n0 + 1) * Nout + mC0] = acc1[nf][1] + bC0;
        }
        if (vC1) {
            os[(size_t)n0 * Nout + mC1]       = acc1[nf][2] + bC1;
            os[(size_t)(n0 + 1) * Nout + mC1] = acc1[nf][3] + bC1;
        }
    }
}

// ================= small kernels =================
__global__ void k_embed(const int* __restrict__ idx, const float* __restrict__ emb,
                        float* __restrict__ x) {
    int b = blockIdx.x;
    const float4* src = (const float4*)(emb + (size_t)idx[b] * HH);
    float4* dst = (float4*)(x + (size_t)b * HH);
    for (int i = threadIdx.x; i < HH / 4; i += blockDim.x) dst[i] = src[i];
}

// GRU gates; sums 4 K-slices of GX/GH, folds biases, writes hidden + next input.
__global__ void k_gates(const float* __restrict__ gx, const float* __restrict__ gh,
                        const float* __restrict__ bih, const float* __restrict__ bhh,
                        const float* __restrict__ hprev,
                        float* __restrict__ out_hid, float* __restrict__ out_next,
                        int next_stride) {
    int i = blockIdx.x * blockDim.x + threadIdx.x;   // 65536 total
    int b = i >> 10, j = i & 1023;
    size_t o = (size_t)b * 3072 + j;
    float gr = bih[j], gz = bih[j + 1024], gn = bih[j + 2048];
    float hr = bhh[j], hz = bhh[j + 1024], hn = bhh[j + 2048];
#pragma unroll
    for (int s = 0; s < 4; ++s) {
        const float* px = gx + (size_t)s * 196608 + o;
        const float* ph = gh + (size_t)s * 196608 + o;
        gr += px[0];   gz += px[1024]; gn += px[2048];
        hr += ph[0];   hz += ph[1024]; hn += ph[2048];
    }
    float r = 1.f / (1.f + __expf(-(gr + hr)));
    float z = 1.f / (1.f + __expf(-(gz + hz)));
    float n = tanhf(gn + r * hn);
    float h = (1.f - z) * n + z * hprev[(size_t)b * 1024 + j];
    out_hid[(size_t)b * 1024 + j] = h;
    out_next[(size_t)b * next_stride + j] = h;
}

__global__ void k_energy(const float* __restrict__ rnn, int rnn_stride,
                         const float* __restrict__ enc, float* __restrict__ E) {
    __shared__ float sx[HH];
    int b = blockIdx.y;
    const float4* src = (const float4*)(rnn + (size_t)b * rnn_stride);
    for (int i = threadIdx.x; i < HH / 4; i += blockDim.x)
        ((float4*)sx)[i] = src[i];
    __syncthreads();
    int wid = threadIdx.x >> 5, lid = threadIdx.x & 31;
    int l = blockIdx.x * 8 + wid;
    const float4* e4 = (const float4*)(enc + ((size_t)l * BB + b) * HH);
    float acc = 0.f;
#pragma unroll
    for (int j = 0; j < 8; ++j) {
        float4 v = __ldg(e4 + lid + j * 32);
        float4 xw = ((const float4*)sx)[lid + j * 32];
        acc += v.x * xw.x + v.y * xw.y + v.z * xw.z + v.w * xw.w;
    }
#pragma unroll
    for (int o = 16; o; o >>= 1) acc += __shfl_xor_sync(0xffffffffu, acc, o);
    if (lid == 0) E[(size_t)b * LLEN + l] = acc;
}

__global__ void k_softmax(float* __restrict__ E, float* __restrict__ attn_out) {
    __shared__ float red[8];
    int b = blockIdx.x;
    float* e = E + (size_t)b * LLEN;
    int tid = threadIdx.x;
    float v[4];
    float m = -1e30f;
#pragma unroll
    for (int j = 0; j < 4; ++j) { v[j] = e[tid + j * 256]; m = fmaxf(m, v[j]); }
#pragma unroll
    for (int o = 16; o; o >>= 1) m = fmaxf(m, __shfl_xor_sync(0xffffffffu, m, o));
    if ((tid & 31) == 0) red[tid >> 5] = m;
    __syncthreads();
    float bm = red[0];
#pragma unroll
    for (int w = 1; w < 8; ++w) bm = fmaxf(bm, red[w]);
    float s = 0.f;
#pragma unroll
    for (int j = 0; j < 4; ++j) { v[j] = __expf(v[j] - bm); s += v[j]; }
#pragma unroll
    for (int o = 16; o; o >>= 1) s += __shfl_xor_sync(0xffffffffu, s, o);
    __syncthreads();
    if ((tid & 31) == 0) red[tid >> 5] = s;
    __syncthreads();
    float bs = 0.f;
#pragma unroll
    for (int w = 0; w < 8; ++w) bs += red[w];
    float inv = 1.f / bs;
#pragma unroll
    for (int j = 0; j < 4; ++j) {
        float a = v[j] * inv;
        e[tid + j * 256] = a;
        attn_out[(size_t)b * LLEN + tid + j * 256] = a;
    }
}

__global__ void k_context(const float* __restrict__ attn, const float* __restrict__ enc,
                          float* __restrict__ ctx, int ctx_stride) {
    __shared__ float sa[LLEN];
    int b = blockIdx.x;
    int h = blockIdx.y * 128 + threadIdx.x;
    for (int i = threadIdx.x; i < LLEN; i += 128)
        sa[i] = attn[(size_t)b * LLEN + i];
    __syncthreads();
    const float* ep = enc + (size_t)b * HH + h;
    float a[8];
#pragma unroll
    for (int j = 0; j < 8; ++j) a[j] = 0.f;
    for (int l = 0; l < LLEN; l += 8) {
#pragma unroll
        for (int j = 0; j < 8; ++j)
            a[j] += sa[l + j] * __ldg(ep + (size_t)(l + j) * (BB * HH));
    }
    float s = ((a[0] + a[1]) + (a[2] + a[3])) + ((a[4] + a[5]) + (a[6] + a[7]));
    ctx[(size_t)b * ctx_stride + h] = s;
}

// ================= launcher =================
extern "C" void kernel_launch(void* const* d_in, const int* in_sizes, int n_in,
                              void* d_out, int out_size) {
    const int*   input_seq = (const int*)  d_in[0];
    const float* last_h    = (const float*)d_in[1];
    const float* enc       = (const float*)d_in[2];
    const float* emb       = (const float*)d_in[3];
    const float* W_ih      = (const float*)d_in[4];
    const float* W_hh      = (const float*)d_in[5];
    const float* b_ih      = (const float*)d_in[6];
    const float* b_hh      = (const float*)d_in[7];
    const float* W_concat  = (const float*)d_in[8];
    const float* b_concat  = (const float*)d_in[9];
    const float* W_out     = (const float*)d_in[10];
    const float* b_out     = (const float*)d_in[11];
    float* out = (float*)d_out;

    float* scratch = nullptr;
    cudaGetSymbolAddress((void**)&scratch, g_scratch);
    float* X     = scratch;
    float* XP    = scratch + 65536;
    float* HP    = scratch + 131072;
    float* GX    = scratch + 196608;
    float* GH    = scratch + 983040;
    float* E     = scratch + 1769472;
    float* CIN   = scratch + 1835008;   // [rnn | ctx], row stride 2048
    float* CINP  = scratch + 1966080;
    float* CC    = scratch + 2097152;   // 4 slices of 64x1024
    float* COUTP = scratch + 2359296;

    float* out_logits = out;                                    // (B, V)
    float* out_hidden = out + (size_t)BB * VV;                  // (NL, B, H)
    float* out_attn   = out_hidden + (size_t)2 * BB * HH;       // (B, 1, L)

    k_embed<<<BB, 256>>>(input_seq, emb, X);

    // ---- GRU layer 0 ----
    k_pack<<<dim3(64, 2), 256>>>(X, XP, last_h, HP, 1024);
    k_gemm<<<dim3(24, 2, 4), 128>>>(
        W_ih, (const uint4*)XP, GX, 3072, 1024, 16, nullptr,
        W_hh, (const uint4*)HP, GH);
    k_gates<<<256, 256>>>(GX, GH, b_ih, b_hh, last_h, out_hidden, X, 1024);

    // ---- GRU layer 1 ----
    k_pack<<<dim3(64, 2), 256>>>(X, XP, last_h + (size_t)BB * HH, HP, 1024);
    k_gemm<<<dim3(24, 2, 4), 128>>>(
        W_ih + (size_t)3072 * 1024, (const uint4*)XP, GX, 3072, 1024, 16, nullptr,
        W_hh + (size_t)3072 * 1024, (const uint4*)HP, GH);
    k_gates<<<256, 256>>>(GX, GH, b_ih + 3072, b_hh + 3072,
                          last_h + (size_t)BB * HH,
                          out_hidden + (size_t)BB * HH, CIN, 2048);

    // ---- attention ----
    k_energy<<<dim3(128, 64), 256>>>(CIN, 2048, enc, E);
    k_softmax<<<64, 256>>>(E, out_attn);
    k_context<<<dim3(64, 8), 128>>>(E, enc, CIN + 1024, 2048);

    // ---- concat GEMM (raw sums into 4 K-slice buffers) ----
    k_pack<<<dim3(128, 1), 256>>>(CIN, CINP, nullptr, nullptr, 2048);
    k_gemm<<<dim3(8, 1, 4), 128>>>(
        W_concat, (const uint4*)CINP, CC, 1024, 2048, 32, nullptr,
        nullptr, nullptr, nullptr);

    // ---- bias + tanh + pack for W_out ----
    k_pack_cout<<<64, 256>>>(CC, b_concat, COUTP);

    // ---- logits ----
    k_gemm<<<dim3(393, 1, 1), 128>>>(
        W_out, (const uint4*)COUTP, out_logits, VV, 1024, 64, b_out,
        nullptr, nullptr, nullptr);

    (void)in_sizes; (void)n_in; (void)out_size;
}

// round 6
// speedup vs baseline: 4.7781x; 1.8528x over previous
#include <cuda_runtime.h>
#include <cuda_bf16.h>
#include <cstdint>

#define HH 1024
#define BB 64
#define LLEN 1024
#define VV 50257

// ---------------- split-bf16 helpers ----------------
__device__ __forceinline__ uint32_t pack_bf16x2(float lo, float hi) {
    uint32_t r;
    asm("cvt.rn.satfinite.bf16x2.f32 %0, %1, %2;" : "=r"(r) : "f"(hi), "f"(lo));
    return r;
}

__device__ __forceinline__ void split2(float2 v, uint32_t& hi, uint32_t& lo) {
    hi = pack_bf16x2(v.x, v.y);
    float lx = v.x - __uint_as_float(hi << 16);
    float ly = v.y - __uint_as_float(hi & 0xFFFF0000u);
    lo = pack_bf16x2(lx, ly);
}

__device__ __forceinline__ void mma16816(float* c,
                                         uint32_t a0, uint32_t a1, uint32_t a2, uint32_t a3,
                                         uint32_t b0, uint32_t b1) {
    asm volatile(
        "mma.sync.aligned.m16n8k16.row.col.f32.bf16.bf16.f32 "
        "{%0,%1,%2,%3}, {%4,%5,%6,%7}, {%8,%9}, {%0,%1,%2,%3};"
        : "+f"(c[0]), "+f"(c[1]), "+f"(c[2]), "+f"(c[3])
        : "r"(a0), "r"(a1), "r"(a2), "r"(a3), "r"(b0), "r"(b1));
}

// ---------------- scratch layout (floats) ----------------
// X 0 | XP 65536 | HP 131072 | GX 196608(786432) | GH 983040(786432)
// E 1769472(65536) | MS 1835008(1024) | PCTX 1836032(524288)
// CIN 2360320(131072) | CINP 2491392(131072) | CC 2622464(8x65536)
// COUTP 3146752(65536) | LOG 3212288(2x3216448)  total 9645184
__device__ float g_scratch[9645184];

// ================= B-operand pack: fp32 -> MMA-ready bf16 hi/lo =================
__global__ void __launch_bounds__(256) k_pack(
    const float* __restrict__ s1, float* __restrict__ d1,
    const float* __restrict__ s2, float* __restrict__ d2, int K)
{
    const float* src = blockIdx.y ? s2 : s1;
    float* dst = blockIdx.y ? d2 : d1;
    int i = blockIdx.x * 256 + threadIdx.x;
    int lane = i & 31, nf = (i >> 5) & 7, t = i >> 8;
    int g = lane >> 2, tig = lane & 3;
    int n = nf * 8 + g;
    int k0 = t * 16 + tig * 2;
    float2 v0 = *(const float2*)(src + (size_t)n * K + k0);
    float2 v1 = *(const float2*)(src + (size_t)n * K + k0 + 8);
    uint32_t h0, l0, h1, l1;
    split2(v0, h0, l0);
    split2(v1, h1, l1);
    ((uint4*)dst)[i] = make_uint4(h0, h1, l0, l1);
}

// sum 8 concat K-slices + bias + tanh, then split-pack for W_out GEMM.
__global__ void __launch_bounds__(256) k_pack_cout(
    const float* __restrict__ cc, const float* __restrict__ bias,
    float* __restrict__ dst)
{
    int i = blockIdx.x * 256 + threadIdx.x;
    int lane = i & 31, nf = (i >> 5) & 7, t = i >> 8;
    int g = lane >> 2, tig = lane & 3;
    int n = nf * 8 + g;
    int k0 = t * 16 + tig * 2;
    size_t base = (size_t)n * HH;
    float e0 = bias[k0], e1 = bias[k0 + 1], e2 = bias[k0 + 8], e3 = bias[k0 + 9];
#pragma unroll
    for (int z = 0; z < 8; ++z) {
        const float* p = cc + (size_t)z * 65536 + base;
        e0 += p[k0]; e1 += p[k0 + 1]; e2 += p[k0 + 8]; e3 += p[k0 + 9];
    }
    e0 = tanhf(e0); e1 = tanhf(e1); e2 = tanhf(e2); e3 = tanhf(e3);
    uint32_t h0, l0, h1, l1;
    split2(make_float2(e0, e1), h0, l0);
    split2(make_float2(e2, e3), h1, l1);
    ((uint4*)dst)[i] = make_uint4(h0, h1, l0, l1);
}

// ================= split-bf16 HMMA GEMM, smem-staged B =================
// out[n][m] = sum_k W[m,k]*X[n,k], n=0..63. 128 threads = 4 warps, warp owns 32 rows.
// blockIdx.y==1 -> second param set; blockIdx.z -> K slice of tps ksteps,
// each slice writes its own 64*Nout buffer.
__global__ void __launch_bounds__(128) k_gemm(
    const float* __restrict__ W, const uint4* __restrict__ P,
    float* __restrict__ out, int Nout, int K, int tps,
    const float* W2, const uint4* P2, float* out2)
{
    if (blockIdx.y == 1) { W = W2; P = P2; out = out2; }

    __shared__ uint4 sb[2][256];

    const int tid = threadIdx.x;
    const int wid = tid >> 5;
    const int lane = tid & 31;
    const int g = lane >> 2;
    const int tig = lane & 3;

    const int mb = blockIdx.x * 128 + wid * 32;
    const int mA0 = mb + g,      mA1 = mb + 8 + g;
    const int mC0 = mb + 16 + g, mC1 = mb + 24 + g;
    const bool vA0 = mA0 < Nout, vA1 = mA1 < Nout;
    const bool vC0 = mC0 < Nout, vC1 = mC1 < Nout;

    const float* WA0 = W + (size_t)(vA0 ? mA0 : 0) * K;
    const float* WA1 = W + (size_t)(vA1 ? mA1 : 0) * K;
    const float* WC0 = W + (size_t)(vC0 ? mC0 : 0) * K;
    const float* WC1 = W + (size_t)(vC1 ? mC1 : 0) * K;

    float acc0[8][4], acc1[8][4];
#pragma unroll
    for (int nf = 0; nf < 8; ++nf)
#pragma unroll
        for (int j = 0; j < 4; ++j) { acc0[nf][j] = 0.f; acc1[nf][j] = 0.f; }

    const int t0 = blockIdx.z * tps;
    const uint4* Pt = P + (size_t)t0 * 256;
    const float2 z2 = make_float2(0.f, 0.f);

    // prefetch kstep 0 of B
    uint4 r0 = __ldg(Pt + tid), r1 = __ldg(Pt + tid + 128);

    for (int t = 0; t < tps; ++t) {
        const int cur = t & 1;
        sb[cur][tid] = r0;
        sb[cur][tid + 128] = r1;
        if (t + 1 < tps) {
            r0 = __ldg(Pt + (size_t)(t + 1) * 256 + tid);
            r1 = __ldg(Pt + (size_t)(t + 1) * 256 + tid + 128);
        }

        const int k0 = (t0 + t) * 16 + tig * 2;
        float2 fa0 = vA0 ? __ldg((const float2*)(WA0 + k0))     : z2;
        float2 fa2 = vA0 ? __ldg((const float2*)(WA0 + k0 + 8)) : z2;
        float2 fa1 = vA1 ? __ldg((const float2*)(WA1 + k0))     : z2;
        float2 fa3 = vA1 ? __ldg((const float2*)(WA1 + k0 + 8)) : z2;
        float2 fc0 = vC0 ? __ldg((const float2*)(WC0 + k0))     : z2;
        float2 fc2 = vC0 ? __ldg((const float2*)(WC0 + k0 + 8)) : z2;
        float2 fc1 = vC1 ? __ldg((const float2*)(WC1 + k0))     : z2;
        float2 fc3 = vC1 ? __ldg((const float2*)(WC1 + k0 + 8)) : z2;

        __syncthreads();   // sb[cur] visible; prev reads of this buffer done

        uint32_t ah0, al0, ah1, al1, ah2, al2, ah3, al3;
        uint32_t ch0, cl0, ch1, cl1, ch2, cl2, ch3, cl3;
        split2(fa0, ah0, al0); split2(fa1, ah1, al1);
        split2(fa2, ah2, al2); split2(fa3, ah3, al3);
        split2(fc0, ch0, cl0); split2(fc1, ch1, cl1);
        split2(fc2, ch2, cl2); split2(fc3, ch3, cl3);

        uint4 b[8];
#pragma unroll
        for (int nf = 0; nf < 8; ++nf)
            b[nf] = sb[cur][nf * 32 + lane];

#pragma unroll
        for (int nf = 0; nf < 8; ++nf) {
            mma16816(acc0[nf], ah0, ah1, ah2, ah3, b[nf].x, b[nf].y);
            mma16816(acc1[nf], ch0, ch1, ch2, ch3, b[nf].x, b[nf].y);
            mma16816(acc0[nf], ah0, ah1, ah2, ah3, b[nf].z, b[nf].w);
            mma16816(acc1[nf], ch0, ch1, ch2, ch3, b[nf].z, b[nf].w);
            mma16816(acc0[nf], al0, al1, al2, al3, b[nf].x, b[nf].y);
            mma16816(acc1[nf], cl0, cl1, cl2, cl3, b[nf].x, b[nf].y);
        }
    }

    float* os = out + (size_t)blockIdx.z * 64 * Nout;
#pragma unroll
    for (int nf = 0; nf < 8; ++nf) {
        const int n0 = nf * 8 + tig * 2;
        if (vA0) {
            os[(size_t)n0 * Nout + mA0]       = acc0[nf][0];
            os[(size_t)(n0 + 1) * Nout + mA0] = acc0[nf][1];
        }
        if (vA1) {
            os[(size_t)n0 * Nout + mA1]       = acc0[nf][2];
            os[(size_t)(n0 + 1) * Nout + mA1] = acc0[nf][3];
        }
        if (vC0) {
            os[(size_t)n0 * Nout + mC0]       = acc1[nf][0];
            os[(size_t)(n0 + 1) * Nout + mC0] = acc1[nf][1];
        }
        if (vC1) {
            os[(size_t)n0 * Nout + mC1]       = acc1[nf][2];
            os[(size_t)(n0 + 1) * Nout + mC1] = acc1[nf][3];
        }
    }
}

// ================= logits reduce: sum 2 K-slices + bias =================
__global__ void __launch_bounds__(256) k_lred(
    const float* __restrict__ L, const float* __restrict__ bias,
    float* __restrict__ out)
{
    int m = blockIdx.x * 256 + threadIdx.x;
    int n = blockIdx.y;
    if (m < VV) {
        size_t i = (size_t)n * VV + m;
        out[i] = L[i] + L[i + (size_t)64 * VV] + bias[m];
    }
}

// ================= small kernels =================
__global__ void k_embed(const int* __restrict__ idx, const float* __restrict__ emb,
                        float* __restrict__ x) {
    int b = blockIdx.x;
    const float4* src = (const float4*)(emb + (size_t)idx[b] * HH);
    float4* dst = (float4*)(x + (size_t)b * HH);
    for (int i = threadIdx.x; i < HH / 4; i += blockDim.x) dst[i] = src[i];
}

__global__ void k_gates(const float* __restrict__ gx, const float* __restrict__ gh,
                        const float* __restrict__ bih, const float* __restrict__ bhh,
                        const float* __restrict__ hprev,
                        float* __restrict__ out_hid, float* __restrict__ out_next,
                        int next_stride) {
    int i = blockIdx.x * blockDim.x + threadIdx.x;   // 65536
    int b = i >> 10, j = i & 1023;
    size_t o = (size_t)b * 3072 + j;
    float gr = bih[j], gz = bih[j + 1024], gn = bih[j + 2048];
    float hr = bhh[j], hz = bhh[j + 1024], hn = bhh[j + 2048];
#pragma unroll
    for (int s = 0; s < 4; ++s) {
        const float* px = gx + (size_t)s * 196608 + o;
        const float* ph = gh + (size_t)s * 196608 + o;
        gr += px[0];   gz += px[1024]; gn += px[2048];
        hr += ph[0];   hz += ph[1024]; hn += ph[2048];
    }
    float r = 1.f / (1.f + __expf(-(gr + hr)));
    float z = 1.f / (1.f + __expf(-(gz + hz)));
    float n = tanhf(gn + r * hn);
    float h = (1.f - z) * n + z * hprev[(size_t)b * 1024 + j];
    out_hid[(size_t)b * 1024 + j] = h;
    out_next[(size_t)b * next_stride + j] = h;
}

// ============ fused attention: energy + online softmax + partial context ============
// grid (8 chunks, 64 b), 256 threads. Each chunk = 128 L rows in 16-row subchunks
// (phase A energies -> phase B weighted accumulate; phase B re-reads hit L1/L2).
__global__ void __launch_bounds__(256) k_attn_fused(
    const float* __restrict__ rnn, int rnn_stride,
    const float* __restrict__ enc,
    float* __restrict__ E, float* __restrict__ MS, float* __restrict__ PCTX)
{
    __shared__ float sx[HH];
    __shared__ float sce[16];
    const int chunk = blockIdx.x, b = blockIdx.y;
    const int tid = threadIdx.x;
    const int wid = tid >> 5, lane = tid & 31;

    const float4* src = (const float4*)(rnn + (size_t)b * rnn_stride);
    for (int i = tid; i < HH / 4; i += 256)
        ((float4*)sx)[i] = src[i];
    __syncthreads();

    float M = -1e30f, S = 0.f;
    float4 a = make_float4(0.f, 0.f, 0.f, 0.f);
    const float4* sx4 = (const float4*)sx;

    for (int sub = 0; sub < 8; ++sub) {
        const int lbase = chunk * 128 + sub * 16;
        // ---- phase A: 8 warps x 2 rows -> energies ----
#pragma unroll
        for (int j = 0; j < 2; ++j) {
            const int l = lbase + wid * 2 + j;
            const float4* e4 = (const float4*)(enc + ((size_t)l * BB + b) * HH);
            float acc = 0.f;
#pragma unroll
            for (int i = 0; i < 8; ++i) {
                float4 v = __ldg(e4 + lane + i * 32);
                float4 x = sx4[lane + i * 32];
                acc += v.x * x.x + v.y * x.y + v.z * x.z + v.w * x.w;
            }
#pragma unroll
            for (int o = 16; o; o >>= 1) acc += __shfl_xor_sync(0xffffffffu, acc, o);
            if (lane == 0) {
                sce[wid * 2 + j] = acc;
                E[(size_t)b * LLEN + l] = acc;
            }
        }
        __syncthreads();

        // ---- phase B: online softmax + context accumulate ----
        float msub = sce[0];
#pragma unroll
        for (int i = 1; i < 16; ++i) msub = fmaxf(msub, sce[i]);
        float newM = fmaxf(M, msub);
        float scale = __expf(M - newM);
        S *= scale;
        a.x *= scale; a.y *= scale; a.z *= scale; a.w *= scale;
        const float4* encb = (const float4*)enc + (size_t)lbase * BB * 256 + (size_t)b * 256 + tid;
#pragma unroll
        for (int i = 0; i < 16; ++i) {
            float w = __expf(sce[i] - newM);
            S += w;                                  // identical per-thread sum
            float4 v = __ldg(encb + (size_t)i * BB * 256);
            a.x += w * v.x; a.y += w * v.y; a.z += w * v.z; a.w += w * v.w;
        }
        M = newM;
        __syncthreads();
    }

    ((float4*)PCTX)[((size_t)b * 8 + chunk) * 256 + tid] = a;
    if (tid == 0) {
        MS[((size_t)b * 8 + chunk) * 2]     = M;
        MS[((size_t)b * 8 + chunk) * 2 + 1] = S;
    }
}

// combine 8 chunks: global softmax stats, final context, attention weights
__global__ void __launch_bounds__(256) k_attn_combine(
    const float* __restrict__ E, const float* __restrict__ MS,
    const float* __restrict__ PCTX,
    float* __restrict__ ctx, int ctx_stride, float* __restrict__ attn_out)
{
    __shared__ float sm[8], ss[8];
    const int b = blockIdx.x, tid = threadIdx.x;
    if (tid < 8) {
        sm[tid] = MS[((size_t)b * 8 + tid) * 2];
        ss[tid] = MS[((size_t)b * 8 + tid) * 2 + 1];
    }
    __syncthreads();
    float M = sm[0];
#pragma unroll
    for (int c = 1; c < 8; ++c) M = fmaxf(M, sm[c]);
    float S = 0.f;
#pragma unroll
    for (int c = 0; c < 8; ++c) S += ss[c] * __expf(sm[c] - M);
    const float inv = 1.f / S;

    float4 a = make_float4(0.f, 0.f, 0.f, 0.f);
#pragma unroll
    for (int c = 0; c < 8; ++c) {
        float w = __expf(sm[c] - M);
        float4 v = ((const float4*)PCTX)[((size_t)b * 8 + c) * 256 + tid];
        a.x += w * v.x; a.y += w * v.y; a.z += w * v.z; a.w += w * v.w;
    }
    a.x *= inv; a.y *= inv; a.z *= inv; a.w *= inv;
    ((float4*)(ctx + (size_t)b * ctx_stride))[tid] = a;

#pragma unroll
    for (int j = 0; j < 4; ++j) {
        int l = tid + j * 256;
        attn_out[(size_t)b * LLEN + l] = __expf(E[(size_t)b * LLEN + l] - M) * inv;
    }
}

// ================= launcher =================
extern "C" void kernel_launch(void* const* d_in, const int* in_sizes, int n_in,
                              void* d_out, int out_size) {
    const int*   input_seq = (const int*)  d_in[0];
    const float* last_h    = (const float*)d_in[1];
    const float* enc       = (const float*)d_in[2];
    const float* emb       = (const float*)d_in[3];
    const float* W_ih      = (const float*)d_in[4];
    const float* W_hh      = (const float*)d_in[5];
    const float* b_ih      = (const float*)d_in[6];
    const float* b_hh      = (const float*)d_in[7];
    const float* W_concat  = (const float*)d_in[8];
    const float* b_concat  = (const float*)d_in[9];
    const float* W_out     = (const float*)d_in[10];
    const float* b_out     = (const float*)d_in[11];
    float* out = (float*)d_out;

    float* scratch = nullptr;
    cudaGetSymbolAddress((void**)&scratch, g_scratch);
    float* X     = scratch;
    float* XP    = scratch + 65536;
    float* HP    = scratch + 131072;
    float* GX    = scratch + 196608;
    float* GH    = scratch + 983040;
    float* E     = scratch + 1769472;
    float* MS    = scratch + 1835008;
    float* PCTX  = scratch + 1836032;
    float* CIN   = scratch + 2360320;   // [rnn | ctx], row stride 2048
    float* CINP  = scratch + 2491392;
    float* CC    = scratch + 2622464;   // 8 slices of 64x1024
    float* COUTP = scratch + 3146752;
    float* LOG   = scratch + 3212288;   // 2 slices of 64xVV

    float* out_logits = out;
    float* out_hidden = out + (size_t)BB * VV;
    float* out_attn   = out_hidden + (size_t)2 * BB * HH;

    k_embed<<<BB, 256>>>(input_seq, emb, X);

    // ---- GRU layer 0 (4 K-slices x 16 ksteps = K 1024) ----
    k_pack<<<dim3(64, 2), 256>>>(X, XP, last_h, HP, 1024);
    k_gemm<<<dim3(24, 2, 4), 128>>>(
        W_ih, (const uint4*)XP, GX, 3072, 1024, 16,
        W_hh, (const uint4*)HP, GH);
    k_gates<<<256, 256>>>(GX, GH, b_ih, b_hh, last_h, out_hidden, X, 1024);

    // ---- GRU layer 1 ----
    k_pack<<<dim3(64, 2), 256>>>(X, XP, last_h + (size_t)BB * HH, HP, 1024);
    k_gemm<<<dim3(24, 2, 4), 128>>>(
        W_ih + (size_t)3072 * 1024, (const uint4*)XP, GX, 3072, 1024, 16,
        W_hh + (size_t)3072 * 1024, (const uint4*)HP, GH);
    k_gates<<<256, 256>>>(GX, GH, b_ih + 3072, b_hh + 3072,
                          last_h + (size_t)BB * HH,
                          out_hidden + (size_t)BB * HH, CIN, 2048);

    // ---- fused attention ----
    k_attn_fused<<<dim3(8, 64), 256>>>(CIN, 2048, enc, E, MS, PCTX);
    k_attn_combine<<<64, 256>>>(E, MS, PCTX, CIN + 1024, 2048, out_attn);

    // ---- concat GEMM (8 K-slices x 16 ksteps = K 2048) ----
    k_pack<<<dim3(128, 1), 256>>>(CIN, CINP, nullptr, nullptr, 2048);
    k_gemm<<<dim3(8, 1, 8), 128>>>(
        W_concat, (const uint4*)CINP, CC, 1024, 2048, 16,
        nullptr, nullptr, nullptr);
    k_pack_cout<<<64, 256>>>(CC, b_concat, COUTP);

    // ---- logits: split-K x2 (2 x 32 ksteps = K 1024) + reduce(+bias) ----
    k_gemm<<<dim3(393, 1, 2), 128>>>(
        W_out, (const uint4*)COUTP, LOG, VV, 1024, 32,
        nullptr, nullptr, nullptr);
    k_lred<<<dim3(197, 64), 256>>>(LOG, b_out, out_logits);

    (void)in_sizes; (void)n_in; (void)out_size;
}